// round 7
// baseline (speedup 1.0000x reference)
#include <cuda_runtime.h>
#include <cuda_bf16.h>
#include <math.h>
#include <stdint.h>

// Problem constants
#define Bq 2
#define Tq 2048
#define Dq 1024
#define Hq 16
#define DKq 64
#define Mq (Bq*Tq)   // 4096

// ---------------- scratch (device globals; no allocation allowed) ----------
__device__ float g_Q[Mq * Dq];
__device__ float g_K[Mq * Dq];
__device__ float g_V[Mq * Dq];
__device__ float g_C[Mq * Dq];

// ---------------- tf32 helpers ----------------------------------------------
__device__ __forceinline__ uint32_t f2tf32(float f) {
    uint32_t r;
    asm volatile("cvt.rna.tf32.f32 %0, %1;" : "=r"(r) : "f"(f));
    return r;
}

__device__ __forceinline__ void mma_tf32(float c[4],
                                         uint32_t a0, uint32_t a1, uint32_t a2, uint32_t a3,
                                         uint32_t b0, uint32_t b1) {
    asm volatile(
        "mma.sync.aligned.m16n8k8.row.col.f32.tf32.tf32.f32 "
        "{%0,%1,%2,%3}, {%4,%5,%6,%7}, {%8,%9}, {%0,%1,%2,%3};"
        : "+f"(c[0]), "+f"(c[1]), "+f"(c[2]), "+f"(c[3])
        : "r"(a0), "r"(a1), "r"(a2), "r"(a3), "r"(b0), "r"(b1));
}

// ---------------- bf16 helpers ----------------------------------------------
__device__ __forceinline__ uint32_t pack_bf16x2(float x, float y) {
    uint32_t r;
    asm("cvt.rn.bf16x2.f32 %0, %1, %2;" : "=r"(r) : "f"(y), "f"(x));
    return r;
}
__device__ __forceinline__ float bf_lo_f(uint32_t p) { return __uint_as_float(p << 16); }
__device__ __forceinline__ float bf_hi_f(uint32_t p) { return __uint_as_float(p & 0xffff0000u); }

__device__ __forceinline__ void mma_bf16(float c[4],
                                         uint32_t a0, uint32_t a1, uint32_t a2, uint32_t a3,
                                         uint32_t b0, uint32_t b1) {
    asm volatile(
        "mma.sync.aligned.m16n8k16.row.col.f32.bf16.bf16.f32 "
        "{%0,%1,%2,%3}, {%4,%5,%6,%7}, {%8,%9}, {%0,%1,%2,%3};"
        : "+f"(c[0]), "+f"(c[1]), "+f"(c[2]), "+f"(c[3])
        : "r"(a0), "r"(a1), "r"(a2), "r"(a3), "r"(b0), "r"(b1));
}

// ---------------- Pipelined TF32 GEMM: Y = X @ W + bias ----------------------
#define GBM 128
#define GBN 128
#define GBK 16
#define SMP 136

__device__ __forceinline__
void tf32_gemm_body(const float* __restrict__ X,
                    const float* __restrict__ W,
                    const float* __restrict__ bias,
                    float* __restrict__ Y,
                    int M, int N, int K,
                    int bm, int bn)
{
    __shared__ uint32_t As[2][GBK][SMP];
    __shared__ uint32_t Bs[2][GBK][SMP];

    const int tid  = threadIdx.x;
    const int wid  = tid >> 5;
    const int lane = tid & 31;
    const int gr   = lane >> 2;
    const int tc   = lane & 3;

    const int wm = wid & 1;
    const int wn = wid >> 1;

    const int a_r  = tid >> 1;
    const int a_kc = (tid & 1) * 8;
    const int b_r  = tid >> 4;
    const int b_c  = (tid & 15) * 4;

    const float* Xp = X + (size_t)(bm * GBM) * K;
    const float* Wp = W + (size_t)bn * GBN;

    float acc[4][4][4];
#pragma unroll
    for (int i = 0; i < 4; ++i)
#pragma unroll
        for (int j = 0; j < 4; ++j)
#pragma unroll
            for (int f = 0; f < 4; ++f) acc[i][j][f] = 0.f;

    float4 la0, la1, lb0, lb1;

    la0 = *(const float4*)(Xp + (size_t)a_r * K + a_kc);
    la1 = *(const float4*)(Xp + (size_t)a_r * K + a_kc + 4);
    lb0 = *(const float4*)(Wp + (size_t)b_r * N + b_c);
    lb1 = *(const float4*)(Wp + (size_t)b_r * N + b_c + 64);

    {
        As[0][a_kc + 0][a_r] = f2tf32(la0.x);
        As[0][a_kc + 1][a_r] = f2tf32(la0.y);
        As[0][a_kc + 2][a_r] = f2tf32(la0.z);
        As[0][a_kc + 3][a_r] = f2tf32(la0.w);
        As[0][a_kc + 4][a_r] = f2tf32(la1.x);
        As[0][a_kc + 5][a_r] = f2tf32(la1.y);
        As[0][a_kc + 6][a_r] = f2tf32(la1.z);
        As[0][a_kc + 7][a_r] = f2tf32(la1.w);
        uint4 u0, u1;
        u0.x = f2tf32(lb0.x); u0.y = f2tf32(lb0.y);
        u0.z = f2tf32(lb0.z); u0.w = f2tf32(lb0.w);
        u1.x = f2tf32(lb1.x); u1.y = f2tf32(lb1.y);
        u1.z = f2tf32(lb1.z); u1.w = f2tf32(lb1.w);
        *(uint4*)&Bs[0][b_r][b_c]      = u0;
        *(uint4*)&Bs[0][b_r][b_c + 64] = u1;
    }
    __syncthreads();

    int cur = 0;
    for (int k0 = 0; k0 < K; k0 += GBK) {
        const bool has_next = (k0 + GBK < K);
        if (has_next) {
            la0 = *(const float4*)(Xp + (size_t)a_r * K + k0 + GBK + a_kc);
            la1 = *(const float4*)(Xp + (size_t)a_r * K + k0 + GBK + a_kc + 4);
            lb0 = *(const float4*)(Wp + (size_t)(k0 + GBK + b_r) * N + b_c);
            lb1 = *(const float4*)(Wp + (size_t)(k0 + GBK + b_r) * N + b_c + 64);
        }

#pragma unroll
        for (int ks = 0; ks < GBK; ks += 8) {
            uint32_t af[4][4];
            uint32_t bf[4][2];
#pragma unroll
            for (int mt = 0; mt < 4; ++mt) {
                int m0 = wm * 64 + mt * 16;
                af[mt][0] = As[cur][ks + tc][m0 + gr];
                af[mt][1] = As[cur][ks + tc][m0 + gr + 8];
                af[mt][2] = As[cur][ks + tc + 4][m0 + gr];
                af[mt][3] = As[cur][ks + tc + 4][m0 + gr + 8];
            }
#pragma unroll
            for (int nt = 0; nt < 4; ++nt) {
                int n0 = wn * 32 + nt * 8;
                bf[nt][0] = Bs[cur][ks + tc][n0 + gr];
                bf[nt][1] = Bs[cur][ks + tc + 4][n0 + gr];
            }
#pragma unroll
            for (int mt = 0; mt < 4; ++mt)
#pragma unroll
                for (int nt = 0; nt < 4; ++nt)
                    mma_tf32(acc[mt][nt],
                             af[mt][0], af[mt][1], af[mt][2], af[mt][3],
                             bf[nt][0], bf[nt][1]);
        }

        if (has_next) {
            const int nxt = cur ^ 1;
            As[nxt][a_kc + 0][a_r] = f2tf32(la0.x);
            As[nxt][a_kc + 1][a_r] = f2tf32(la0.y);
            As[nxt][a_kc + 2][a_r] = f2tf32(la0.z);
            As[nxt][a_kc + 3][a_r] = f2tf32(la0.w);
            As[nxt][a_kc + 4][a_r] = f2tf32(la1.x);
            As[nxt][a_kc + 5][a_r] = f2tf32(la1.y);
            As[nxt][a_kc + 6][a_r] = f2tf32(la1.z);
            As[nxt][a_kc + 7][a_r] = f2tf32(la1.w);
            uint4 u0, u1;
            u0.x = f2tf32(lb0.x); u0.y = f2tf32(lb0.y);
            u0.z = f2tf32(lb0.z); u0.w = f2tf32(lb0.w);
            u1.x = f2tf32(lb1.x); u1.y = f2tf32(lb1.y);
            u1.z = f2tf32(lb1.z); u1.w = f2tf32(lb1.w);
            *(uint4*)&Bs[nxt][b_r][b_c]      = u0;
            *(uint4*)&Bs[nxt][b_r][b_c + 64] = u1;
            __syncthreads();
            cur = nxt;
        }
    }

#pragma unroll
    for (int mt = 0; mt < 4; ++mt) {
        int row = bm * GBM + wm * 64 + mt * 16 + gr;
#pragma unroll
        for (int nt = 0; nt < 4; ++nt) {
            int col = bn * GBN + wn * 32 + nt * 8 + 2 * tc;
            float b0 = bias[col], b1 = bias[col + 1];
            float2 lo, hi;
            lo.x = acc[mt][nt][0] + b0; lo.y = acc[mt][nt][1] + b1;
            hi.x = acc[mt][nt][2] + b0; hi.y = acc[mt][nt][3] + b1;
            *(float2*)(Y + (size_t)row * N + col)       = lo;
            *(float2*)(Y + (size_t)(row + 8) * N + col) = hi;
        }
    }
}

__global__ __launch_bounds__(256, 2)
void tf32_gemm_kernel(const float* __restrict__ X,
                      const float* __restrict__ W,
                      const float* __restrict__ bias,
                      float* __restrict__ Y,
                      int M, int N, int K)
{
    tf32_gemm_body(X, W, bias, Y, M, N, K, blockIdx.y, blockIdx.x);
}

__global__ __launch_bounds__(256, 2)
void tf32_qkv_kernel(const float* __restrict__ X,
                     const float* __restrict__ Wq, const float* __restrict__ bqv,
                     const float* __restrict__ Wk, const float* __restrict__ bkv,
                     const float* __restrict__ Wv, const float* __restrict__ bvv,
                     float* __restrict__ Qo, float* __restrict__ Ko, float* __restrict__ Vo)
{
    const float* W; const float* bias; float* Y;
    if (blockIdx.z == 0)      { W = Wq; bias = bqv; Y = Qo; }
    else if (blockIdx.z == 1) { W = Wk; bias = bkv; Y = Ko; }
    else                      { W = Wv; bias = bvv; Y = Vo; }
    tf32_gemm_body(X, W, bias, Y, Mq, Dq, Dq, blockIdx.y, blockIdx.x);
}

// ---------------- bf16-split tensor-core flash attention (causal) -----------
// Interleaved smem layout: one LDS.128 yields {hi[tc], hi[tc+4], lo[tc], lo[tc+4]}.
// Row stride 80 u32 -> bank-group (4*gr + tc) mod 8 is conflict-free per phase.
#define AQT 128
#define AKT 64
#define SKW 80    // u32 row stride for interleaved K/V buffers

__global__ __launch_bounds__(256, 2)
void attn_bf_kernel(const float* __restrict__ Q,
                    const float* __restrict__ K,
                    const float* __restrict__ V,
                    float* __restrict__ Ctx)
{
    __shared__ uint32_t Kbuf[64 * SKW];   // Kbuf[key][interleaved dpairs]
    __shared__ uint32_t Vbuf[64 * SKW];   // Vbuf[d][interleaved keypairs]

    const int b  = blockIdx.z;
    const int h  = blockIdx.y;
    const int qb = gridDim.x - 1 - blockIdx.x;   // heavy blocks first
    const int tid  = threadIdx.x;
    const int wid  = tid >> 5;
    const int lane = tid & 31;
    const int gr   = lane >> 2;
    const int tc   = lane & 3;

    const int qrow0 = qb * AQT;
    const float* Qg = Q + ((size_t)b * Tq + qrow0) * Dq + h * DKq;

    uint32_t qh[4][4], ql[4][4];
    {
        const int rbase = wid * 16;
#pragma unroll
        for (int kk = 0; kk < 4; ++kk) {
#pragma unroll
            for (int f = 0; f < 4; ++f) {
                int r = rbase + gr + (f & 1) * 8;
                int c = kk * 16 + 2 * tc + (f >> 1) * 8;
                float2 v = *(const float2*)(Qg + (size_t)r * Dq + c);
                v.x *= 0.125f; v.y *= 0.125f;
                uint32_t hpk = pack_bf16x2(v.x, v.y);
                qh[kk][f] = hpk;
                ql[kk][f] = pack_bf16x2(v.x - bf_lo_f(hpk), v.y - bf_hi_f(hpk));
            }
        }
    }

    float oacc[8][4];
#pragma unroll
    for (int n = 0; n < 8; ++n)
#pragma unroll
        for (int f = 0; f < 4; ++f) oacc[n][f] = 0.f;
    float m0 = -INFINITY, m1 = -INFINITY, l0 = 0.f, l1 = 0.f;

    const int row0g = qrow0 + wid * 16 + gr;
    const int row1g = row0g + 8;
    const int kbmax = (qb + 1) * 2;

    for (int kb = 0; kb < kbmax; ++kb) {
        const float* Kg = K + ((size_t)b * Tq + kb * AKT) * Dq + h * DKq;
        const float* Vg = V + ((size_t)b * Tq + kb * AKT) * Dq + h * DKq;

        // K: key r, dpair dp -> interleaved positions
        for (int i = tid; i < 64 * 32; i += 256) {
            int r = i >> 5, dp = i & 31;
            float2 v = *(const float2*)(Kg + (size_t)r * Dq + 2 * dp);
            uint32_t hpk = pack_bf16x2(v.x, v.y);
            uint32_t lpk = pack_bf16x2(v.x - bf_lo_f(hpk), v.y - bf_hi_f(hpk));
            int pos = r * SKW + ((dp >> 3) << 4) + ((dp & 3) << 2) + ((dp >> 2) & 1);
            Kbuf[pos]     = hpk;
            Kbuf[pos + 2] = lpk;
        }
        // V transposed: element (key r, d) -> bf16 halves of interleaved words
        {
            __nv_bfloat16* Vb = (__nv_bfloat16*)Vbuf;
            for (int i = tid; i < 64 * 64; i += 256) {
                int r = i >> 6, d = i & 63;
                float v = Vg[(size_t)r * Dq + d];
                __nv_bfloat16 hb = __float2bfloat16(v);
                float lo = v - __bfloat162float(hb);
                int dp = r >> 1;
                int pos = d * SKW + ((dp >> 3) << 4) + ((dp & 3) << 2) + ((dp >> 2) & 1);
                Vb[2 * pos + (r & 1)]     = hb;
                Vb[2 * (pos + 2) + (r & 1)] = __float2bfloat16(lo);
            }
        }
        __syncthreads();

        const bool active = (kb * AKT <= qrow0 + wid * 16 + 15);

        if (active) {
            float sacc[8][4];
#pragma unroll
            for (int n = 0; n < 8; ++n)
#pragma unroll
                for (int f = 0; f < 4; ++f) sacc[n][f] = 0.f;

#pragma unroll
            for (int kk = 0; kk < 4; ++kk) {
#pragma unroll
                for (int n = 0; n < 8; ++n) {
                    uint4 kf = *(const uint4*)&Kbuf[(n * 8 + gr) * SKW + (kk << 4) + (tc << 2)];
                    mma_bf16(sacc[n], qh[kk][0], qh[kk][1], qh[kk][2], qh[kk][3], kf.x, kf.y);
                    mma_bf16(sacc[n], ql[kk][0], ql[kk][1], ql[kk][2], ql[kk][3], kf.x, kf.y);
                    mma_bf16(sacc[n], qh[kk][0], qh[kk][1], qh[kk][2], qh[kk][3], kf.z, kf.w);
                }
            }

            if (kb * AKT + AKT - 1 > row0g) {
#pragma unroll
                for (int n = 0; n < 8; ++n) {
                    int colg = kb * AKT + n * 8 + 2 * tc;
                    if (colg     > row0g) sacc[n][0] = -INFINITY;
                    if (colg + 1 > row0g) sacc[n][1] = -INFINITY;
                    if (colg     > row1g) sacc[n][2] = -INFINITY;
                    if (colg + 1 > row1g) sacc[n][3] = -INFINITY;
                }
            }

            float rmax0 = -INFINITY, rmax1 = -INFINITY;
#pragma unroll
            for (int n = 0; n < 8; ++n) {
                rmax0 = fmaxf(rmax0, fmaxf(sacc[n][0], sacc[n][1]));
                rmax1 = fmaxf(rmax1, fmaxf(sacc[n][2], sacc[n][3]));
            }
#pragma unroll
            for (int off = 1; off < 4; off <<= 1) {
                rmax0 = fmaxf(rmax0, __shfl_xor_sync(0xffffffffu, rmax0, off));
                rmax1 = fmaxf(rmax1, __shfl_xor_sync(0xffffffffu, rmax1, off));
            }

            float mn0 = fmaxf(m0, rmax0);
            float mn1 = fmaxf(m1, rmax1);
            float alpha0 = __expf(m0 - mn0);
            float alpha1 = __expf(m1 - mn1);

            float rsum0 = 0.f, rsum1 = 0.f;
#pragma unroll
            for (int n = 0; n < 8; ++n) {
                sacc[n][0] = __expf(sacc[n][0] - mn0);
                sacc[n][1] = __expf(sacc[n][1] - mn0);
                sacc[n][2] = __expf(sacc[n][2] - mn1);
                sacc[n][3] = __expf(sacc[n][3] - mn1);
                rsum0 += sacc[n][0] + sacc[n][1];
                rsum1 += sacc[n][2] + sacc[n][3];
            }
#pragma unroll
            for (int off = 1; off < 4; off <<= 1) {
                rsum0 += __shfl_xor_sync(0xffffffffu, rsum0, off);
                rsum1 += __shfl_xor_sync(0xffffffffu, rsum1, off);
            }

            m0 = mn0; m1 = mn1;
            l0 = l0 * alpha0 + rsum0;
            l1 = l1 * alpha1 + rsum1;
#pragma unroll
            for (int n = 0; n < 8; ++n) {
                oacc[n][0] *= alpha0; oacc[n][1] *= alpha0;
                oacc[n][2] *= alpha1; oacc[n][3] *= alpha1;
            }

#pragma unroll
            for (int kkp = 0; kkp < 4; ++kkp) {
                float* pa = sacc[2 * kkp];
                float* pb = sacc[2 * kkp + 1];
                uint32_t ph0 = pack_bf16x2(pa[0], pa[1]);
                uint32_t ph1 = pack_bf16x2(pa[2], pa[3]);
                uint32_t ph2 = pack_bf16x2(pb[0], pb[1]);
                uint32_t ph3 = pack_bf16x2(pb[2], pb[3]);
                uint32_t pl0 = pack_bf16x2(pa[0] - bf_lo_f(ph0), pa[1] - bf_hi_f(ph0));
                uint32_t pl1 = pack_bf16x2(pa[2] - bf_lo_f(ph1), pa[3] - bf_hi_f(ph1));
                uint32_t pl2 = pack_bf16x2(pb[0] - bf_lo_f(ph2), pb[1] - bf_hi_f(ph2));
                uint32_t pl3 = pack_bf16x2(pb[2] - bf_lo_f(ph3), pb[3] - bf_hi_f(ph3));
#pragma unroll
                for (int n = 0; n < 8; ++n) {
                    uint4 vf = *(const uint4*)&Vbuf[(n * 8 + gr) * SKW + (kkp << 4) + (tc << 2)];
                    mma_bf16(oacc[n], ph0, ph1, ph2, ph3, vf.x, vf.y);
                    mma_bf16(oacc[n], pl0, pl1, pl2, pl3, vf.x, vf.y);
                    mma_bf16(oacc[n], ph0, ph1, ph2, ph3, vf.z, vf.w);
                }
            }
        }
        __syncthreads();
    }

    float inv0 = 1.f / l0;
    float inv1 = 1.f / l1;
    float* Cg = Ctx + ((size_t)b * Tq + qrow0) * Dq + h * DKq;
    const int r0 = wid * 16 + gr;
#pragma unroll
    for (int n = 0; n < 8; ++n) {
        int c = n * 8 + 2 * tc;
        float2 v0, v1;
        v0.x = oacc[n][0] * inv0; v0.y = oacc[n][1] * inv0;
        v1.x = oacc[n][2] * inv1; v1.y = oacc[n][3] * inv1;
        *(float2*)(Cg + (size_t)r0 * Dq + c)       = v0;
        *(float2*)(Cg + (size_t)(r0 + 8) * Dq + c) = v1;
    }
}

// ---------------- launch ----------------------------------------------------
extern "C" void kernel_launch(void* const* d_in, const int* in_sizes, int n_in,
                              void* d_out, int out_size)
{
    const float* x  = (const float*)d_in[0];
    const float* Wq = (const float*)d_in[1];
    const float* bq = (const float*)d_in[2];
    const float* Wk = (const float*)d_in[3];
    const float* bk = (const float*)d_in[4];
    const float* Wv = (const float*)d_in[5];
    const float* bv = (const float*)d_in[6];
    const float* Wo = (const float*)d_in[7];
    const float* bo = (const float*)d_in[8];
    float* out = (float*)d_out;

    float *pQ, *pK, *pV, *pC;
    cudaGetSymbolAddress((void**)&pQ, g_Q);
    cudaGetSymbolAddress((void**)&pK, g_K);
    cudaGetSymbolAddress((void**)&pV, g_V);
    cudaGetSymbolAddress((void**)&pC, g_C);

    dim3 bGemm(256);

    dim3 gQKV(Dq / GBN, Mq / GBM, 3);
    tf32_qkv_kernel<<<gQKV, bGemm>>>(x, Wq, bq, Wk, bk, Wv, bv, pQ, pK, pV);

    dim3 gAttn(Tq / AQT, Hq, Bq);    // (16, 16, 2)
    attn_bf_kernel<<<gAttn, 256>>>(pQ, pK, pV, pC);

    dim3 gGemm(Dq / GBN, Mq / GBM);
    tf32_gemm_kernel<<<gGemm, bGemm>>>(pC, Wo, bo, out, Mq, Dq, Dq);
}